// round 2
// baseline (speedup 1.0000x reference)
#include <cuda_runtime.h>
#include <cuda_bf16.h>
#include <math_constants.h>

// Problem constants
#define B_DIM 1024
#define D_DIM 2048
#define P_DIM 16384
#define TEMP_INV 20.0f      // 1/0.05
#define MOMENTUM 0.2f

// 64 MB logits scratch (allowed: __device__ global, no runtime alloc)
__device__ float g_logits[(size_t)B_DIM * P_DIM];
// Normalized labels (dtype-agnostic ingestion)
__device__ int g_labels[B_DIM];

// ---------------------------------------------------------------------------
// Kernel 0: zero the loss accumulator + ingest labels (int32 OR int64 buffer).
// Detector: labels are < 16384, so if the buffer is int64 every hi-word is 0.
// If it's int32, the "hi words" are the odd-indexed labels (all-zero prob ~0).
// Only reads the first 512 bytes for detection — in bounds either way.
// ---------------------------------------------------------------------------
__global__ void prologue_kernel(const void* __restrict__ raw_labels,
                                float* __restrict__ loss)
{
    if (threadIdx.x == 0 && blockIdx.x == 0) *loss = 0.0f;

    const int* as32 = (const int*)raw_labels;
    __shared__ int is64;
    if (threadIdx.x == 0) {
        int all_hi_zero = 1;
        for (int i = 0; i < 64; ++i)
            if (as32[2 * i + 1] != 0) { all_hi_zero = 0; break; }
        is64 = all_hi_zero;
    }
    __syncthreads();

    if (is64) {
        const long long* as64 = (const long long*)raw_labels;
        for (int i = threadIdx.x; i < B_DIM; i += blockDim.x)
            g_labels[i] = (int)as64[i];
    } else {
        for (int i = threadIdx.x; i < B_DIM; i += blockDim.x)
            g_labels[i] = as32[i];
    }
}

// ---------------------------------------------------------------------------
// Kernel 1: SGEMM  C[b,p] = 20 * dot(X[b,:], S[p,:])
// X: [1024 x 2048] row-major, S: [16384 x 2048] row-major (both K-contiguous)
// 128x128 block tile, BK=16, 256 threads, 8x8 per-thread micro tile.
// ---------------------------------------------------------------------------
__global__ __launch_bounds__(256) void gemm_logits_kernel(
    const float* __restrict__ A,   // X
    const float* __restrict__ Bm)  // storage
{
    __shared__ float As[16][132];
    __shared__ float Bs[16][132];

    const int tid = threadIdx.x;
    const int tx = tid & 15;        // n sub-tile
    const int ty = tid >> 4;        // m sub-tile
    const int m0 = blockIdx.y * 128;
    const int n0 = blockIdx.x * 128;

    float acc[8][8];
#pragma unroll
    for (int i = 0; i < 8; ++i)
#pragma unroll
        for (int j = 0; j < 8; ++j) acc[i][j] = 0.0f;

    for (int k0 = 0; k0 < D_DIM; k0 += 16) {
#pragma unroll
        for (int l = 0; l < 2; ++l) {
            int f = tid + l * 256;        // 512 float4s per operand tile
            int row = f >> 2;
            int kv = (f & 3) << 2;
            float4 va = *(const float4*)(A + (size_t)(m0 + row) * D_DIM + k0 + kv);
            As[kv + 0][row] = va.x; As[kv + 1][row] = va.y;
            As[kv + 2][row] = va.z; As[kv + 3][row] = va.w;
            float4 vb = *(const float4*)(Bm + (size_t)(n0 + row) * D_DIM + k0 + kv);
            Bs[kv + 0][row] = vb.x; Bs[kv + 1][row] = vb.y;
            Bs[kv + 2][row] = vb.z; Bs[kv + 3][row] = vb.w;
        }
        __syncthreads();

#pragma unroll
        for (int kk = 0; kk < 16; ++kk) {
            float a[8], b[8];
#pragma unroll
            for (int i = 0; i < 8; ++i) a[i] = As[kk][ty * 8 + i];
#pragma unroll
            for (int j = 0; j < 8; ++j) b[j] = Bs[kk][tx * 8 + j];
#pragma unroll
            for (int i = 0; i < 8; ++i)
#pragma unroll
                for (int j = 0; j < 8; ++j) acc[i][j] = fmaf(a[i], b[j], acc[i][j]);
        }
        __syncthreads();
    }

#pragma unroll
    for (int i = 0; i < 8; ++i) {
        size_t row = (size_t)(m0 + ty * 8 + i) * P_DIM + n0 + tx * 8;
#pragma unroll
        for (int j = 0; j < 8; ++j)
            g_logits[row + j] = acc[i][j] * TEMP_INV;
    }
}

// ---------------------------------------------------------------------------
// Kernel 2: per-row logsumexp + NLL contribution (one block per batch row)
// ---------------------------------------------------------------------------
__global__ __launch_bounds__(256) void lse_loss_kernel(float* __restrict__ loss)
{
    const int b = blockIdx.x;
    const int tid = threadIdx.x;
    const float* row = g_logits + (size_t)b * P_DIM;
    __shared__ float sh[256];

    // pass 1: max
    float mx = -CUDART_INF_F;
    for (int i = tid; i < P_DIM; i += 256) mx = fmaxf(mx, row[i]);
    sh[tid] = mx; __syncthreads();
    for (int s = 128; s > 0; s >>= 1) {
        if (tid < s) sh[tid] = fmaxf(sh[tid], sh[tid + s]);
        __syncthreads();
    }
    const float m = sh[0];
    __syncthreads();

    // pass 2: sum exp
    float acc = 0.0f;
    for (int i = tid; i < P_DIM; i += 256) acc += __expf(row[i] - m);
    sh[tid] = acc; __syncthreads();
    for (int s = 128; s > 0; s >>= 1) {
        if (tid < s) sh[tid] += sh[tid + s];
        __syncthreads();
    }

    if (tid == 0) {
        float lse = m + logf(sh[0]);
        float tgt = row[g_labels[b]];
        atomicAdd(loss, (lse - tgt) * (1.0f / (float)B_DIM));
    }
}

// ---------------------------------------------------------------------------
// Kernel 3: copy storage -> output (scalar stores: out storage base is d_out+1,
// which is only 4-byte aligned)
// ---------------------------------------------------------------------------
__global__ __launch_bounds__(256) void copy_storage_kernel(
    const float* __restrict__ S, float* __restrict__ outS)
{
    size_t base = (size_t)blockIdx.x * 1024 + threadIdx.x;
#pragma unroll
    for (int k = 0; k < 4; ++k) {
        size_t idx = base + (size_t)k * 256;
        outS[idx] = S[idx];
    }
}

// ---------------------------------------------------------------------------
// Kernel 4: sequential momentum-EMA scatter + renorm.
// One block per batch index; only the FIRST occurrence of each label runs the
// whole chain for that label (duplicates compound sequentially, matching scan).
// ---------------------------------------------------------------------------
__global__ __launch_bounds__(256) void ema_update_kernel(
    const float* __restrict__ X,
    const float* __restrict__ S,
    float* __restrict__ outS)
{
    const int b = blockIdx.x;
    const int lab = g_labels[b];

    // first-occurrence check (uniform across block)
    for (int b2 = 0; b2 < b; ++b2)
        if (g_labels[b2] == lab) return;

    const int tid = threadIdx.x;
    __shared__ float sh[256];

    float r[8];
    const float* srow = S + (size_t)lab * D_DIM;
#pragma unroll
    for (int i = 0; i < 8; ++i) r[i] = srow[tid + i * 256];

    for (int b2 = b; b2 < B_DIM; ++b2) {
        if (g_labels[b2] != lab) continue;
        const float* x = X + (size_t)b2 * D_DIM;
        float ss = 0.0f;
#pragma unroll
        for (int i = 0; i < 8; ++i) {
            r[i] = MOMENTUM * r[i] + (1.0f - MOMENTUM) * x[tid + i * 256];
            ss = fmaf(r[i], r[i], ss);
        }
        sh[tid] = ss; __syncthreads();
        for (int s = 128; s > 0; s >>= 1) {
            if (tid < s) sh[tid] += sh[tid + s];
            __syncthreads();
        }
        float inv = 1.0f / sqrtf(sh[0]);
        __syncthreads();
#pragma unroll
        for (int i = 0; i < 8; ++i) r[i] *= inv;
    }

    float* orow = outS + (size_t)lab * D_DIM;
#pragma unroll
    for (int i = 0; i < 8; ++i) orow[tid + i * 256] = r[i];
}

// ---------------------------------------------------------------------------
extern "C" void kernel_launch(void* const* d_in, const int* in_sizes, int n_in,
                              void* d_out, int out_size)
{
    const float* X      = (const float*)d_in[0];
    const float* S      = (const float*)d_in[1];
    // d_in[2] camids, d_in[3] proxy_labels: unused by the computation
    const void*  alabel = d_in[4];

    float* out   = (float*)d_out;
    float* loss  = out;       // out[0]
    float* outS  = out + 1;   // out[1 .. 1+16384*2048)

    prologue_kernel<<<1, 256>>>(alabel, loss);

    dim3 ggrid(P_DIM / 128, B_DIM / 128);   // 128 x 8
    gemm_logits_kernel<<<ggrid, 256>>>(X, S);

    lse_loss_kernel<<<B_DIM, 256>>>(loss);

    copy_storage_kernel<<<(P_DIM * D_DIM) / 1024, 256>>>(S, outS);

    ema_update_kernel<<<B_DIM, 256>>>(X, S, outS);
}

// round 5
// speedup vs baseline: 1.7779x; 1.7779x over previous
#include <cuda_runtime.h>
#include <cuda_bf16.h>
#include <math_constants.h>
#include <cstdint>

// Problem constants
#define B_DIM 1024
#define D_DIM 2048
#define P_DIM 16384
#define TEMP_INV 20.0f      // 1/0.05
#define MOMENTUM 0.2f

// ---------------- device scratch (static: no runtime alloc) ----------------
__device__ float g_logits[(size_t)B_DIM * P_DIM];                 // 64 MB
__device__ int   g_labels[B_DIM];
__device__ __nv_bfloat16 g_Ah[(size_t)B_DIM * D_DIM];             // 4 MB
__device__ __nv_bfloat16 g_Al[(size_t)B_DIM * D_DIM];             // 4 MB
__device__ __nv_bfloat16 g_Sh[(size_t)P_DIM * D_DIM];             // 64 MB
__device__ __nv_bfloat16 g_Sl[(size_t)P_DIM * D_DIM];             // 64 MB

// ---------------- helpers ----------------
__device__ __forceinline__ uint32_t smem_to_u32(const void* p) {
    uint32_t a;
    asm("{ .reg .u64 t; cvta.to.shared.u64 t, %1; cvt.u32.u64 %0, t; }"
        : "=r"(a) : "l"(p));
    return a;
}

__device__ __forceinline__ void ldsm_x4(uint32_t& r0, uint32_t& r1,
                                        uint32_t& r2, uint32_t& r3,
                                        uint32_t addr) {
    asm volatile("ldmatrix.sync.aligned.m8n8.x4.shared.b16 {%0,%1,%2,%3}, [%4];"
                 : "=r"(r0), "=r"(r1), "=r"(r2), "=r"(r3) : "r"(addr));
}

__device__ __forceinline__ void mma_bf16(float* d, const uint32_t* a,
                                         uint32_t b0, uint32_t b1) {
    asm volatile(
        "mma.sync.aligned.m16n8k16.row.col.f32.bf16.bf16.f32 "
        "{%0,%1,%2,%3}, {%4,%5,%6,%7}, {%8,%9}, {%0,%1,%2,%3};"
        : "+f"(d[0]), "+f"(d[1]), "+f"(d[2]), "+f"(d[3])
        : "r"(a[0]), "r"(a[1]), "r"(a[2]), "r"(a[3]), "r"(b0), "r"(b1));
}

__device__ __forceinline__ void cp_async16(uint32_t dst, const void* src) {
    asm volatile("cp.async.cg.shared.global [%0], [%1], 16;"
                 :: "r"(dst), "l"(src));
}

// ---------------------------------------------------------------------------
// Kernel 0: zero loss + ingest labels (int32 OR int64 buffer, auto-detected)
// ---------------------------------------------------------------------------
__global__ void prologue_kernel(const void* __restrict__ raw_labels,
                                float* __restrict__ loss)
{
    if (threadIdx.x == 0) *loss = 0.0f;

    const int* as32 = (const int*)raw_labels;
    __shared__ int is64;
    if (threadIdx.x == 0) {
        int all_hi_zero = 1;
        for (int i = 0; i < 64; ++i)
            if (as32[2 * i + 1] != 0) { all_hi_zero = 0; break; }
        is64 = all_hi_zero;
    }
    __syncthreads();

    if (is64) {
        const long long* as64 = (const long long*)raw_labels;
        for (int i = threadIdx.x; i < B_DIM; i += blockDim.x)
            g_labels[i] = (int)as64[i];
    } else {
        for (int i = threadIdx.x; i < B_DIM; i += blockDim.x)
            g_labels[i] = as32[i];
    }
}

// ---------------------------------------------------------------------------
// Kernel 1: fp32 -> bf16 hi/lo split (vectorized)
// ---------------------------------------------------------------------------
__global__ __launch_bounds__(256) void split_kernel(
    const float* __restrict__ src,
    __nv_bfloat16* __restrict__ hi,
    __nv_bfloat16* __restrict__ lo)
{
    size_t i = (size_t)blockIdx.x * 256 + threadIdx.x;   // float4 index
    float4 v = ((const float4*)src)[i];
    __nv_bfloat16 h0 = __float2bfloat16(v.x);
    __nv_bfloat16 h1 = __float2bfloat16(v.y);
    __nv_bfloat16 h2 = __float2bfloat16(v.z);
    __nv_bfloat16 h3 = __float2bfloat16(v.w);
    __nv_bfloat16 l0 = __float2bfloat16(v.x - __bfloat162float(h0));
    __nv_bfloat16 l1 = __float2bfloat16(v.y - __bfloat162float(h1));
    __nv_bfloat16 l2 = __float2bfloat16(v.z - __bfloat162float(h2));
    __nv_bfloat16 l3 = __float2bfloat16(v.w - __bfloat162float(h3));
    ushort4 ph = make_ushort4(*(unsigned short*)&h0, *(unsigned short*)&h1,
                              *(unsigned short*)&h2, *(unsigned short*)&h3);
    ushort4 pl = make_ushort4(*(unsigned short*)&l0, *(unsigned short*)&l1,
                              *(unsigned short*)&l2, *(unsigned short*)&l3);
    ((ushort4*)hi)[i] = ph;
    ((ushort4*)lo)[i] = pl;
}

// ---------------------------------------------------------------------------
// Kernel 2: classic-tensor-core GEMM  logits = 20 * (xh·sh + xh·sl + xl·sh)
// CTA 128x128, BK=32, 8 warps (warp tile 32x64), mma.m16n8k16 bf16,
// 2-stage cp.async pipeline, padded SMEM (stride 40 elems = 80B).
// ---------------------------------------------------------------------------
#define ASTRIDE 40            // bf16 elements per padded row (80 bytes)
#define N_CHUNKS 192          // 3 passes x (2048 / 32)

__global__ __launch_bounds__(256, 2) void gemm_mma_kernel()
{
    __shared__ __nv_bfloat16 As[2][128 * ASTRIDE];
    __shared__ __nv_bfloat16 Bs[2][128 * ASTRIDE];

    const int tid  = threadIdx.x;
    const int lane = tid & 31;
    const int wid  = tid >> 5;
    const int wm   = wid & 3;        // 4 m-warps (32 rows each)
    const int wn   = wid >> 2;       // 2 n-warps (64 cols each)
    const int m0   = blockIdx.x * 128;
    const int n0   = blockIdx.y * 128;

    const uint32_t as_base[2] = { smem_to_u32(As[0]), smem_to_u32(As[1]) };
    const uint32_t bs_base[2] = { smem_to_u32(Bs[0]), smem_to_u32(Bs[1]) };

    // cp.async chunk mapping: 512 x 16B per tile; thread handles chunks tid, tid+256
    const int c0r = tid >> 2, c0c = tid & 3;           // chunk tid
    const int c1r = (tid + 256) >> 2, c1c = tid & 3;   // chunk tid+256
    const uint32_t a_sm0 = (uint32_t)(c0r * 80 + c0c * 16);
    const uint32_t a_sm1 = (uint32_t)(c1r * 80 + c1c * 16);

    // ldmatrix lane-invariant offsets
    const uint32_t a_lds = (uint32_t)((wm * 32 + (lane & 15)) * 80 + (lane >> 4) * 16);
    const uint32_t b_lds = (uint32_t)((wn * 64 + (lane & 7) + ((lane >> 3) & 1) * 8) * 80
                                      + (lane >> 4) * 16);

    float d[2][8][4];
#pragma unroll
    for (int t = 0; t < 2; ++t)
#pragma unroll
        for (int j = 0; j < 8; ++j)
#pragma unroll
            for (int k = 0; k < 4; ++k) d[t][j][k] = 0.0f;

    // chunk -> (A ptr, B ptr, k offset)
    auto issue = [&](int c, int stage) {
        const __nv_bfloat16 *pa, *pb;
        int seg = c >> 6;
        if (seg == 0)      { pa = g_Ah; pb = g_Sh; }
        else if (seg == 1) { pa = g_Ah; pb = g_Sl; }
        else               { pa = g_Al; pb = g_Sh; }
        const int kk = (c & 63) << 5;   // *32
        cp_async16(as_base[stage] + a_sm0,
                   pa + (size_t)(m0 + c0r) * D_DIM + kk + c0c * 8);
        cp_async16(as_base[stage] + a_sm1,
                   pa + (size_t)(m0 + c1r) * D_DIM + kk + c1c * 8);
        cp_async16(bs_base[stage] + a_sm0,
                   pb + (size_t)(n0 + c0r) * D_DIM + kk + c0c * 8);
        cp_async16(bs_base[stage] + a_sm1,
                   pb + (size_t)(n0 + c1r) * D_DIM + kk + c1c * 8);
        asm volatile("cp.async.commit_group;");
    };

    issue(0, 0);

    for (int c = 0; c < N_CHUNKS; ++c) {
        const int stage = c & 1;
        if (c + 1 < N_CHUNKS) {
            issue(c + 1, stage ^ 1);
            asm volatile("cp.async.wait_group 1;");
        } else {
            asm volatile("cp.async.wait_group 0;");
        }
        __syncthreads();

#pragma unroll
        for (int ks = 0; ks < 2; ++ks) {
            uint32_t a[2][4];
#pragma unroll
            for (int t = 0; t < 2; ++t)
                ldsm_x4(a[t][0], a[t][1], a[t][2], a[t][3],
                        as_base[stage] + a_lds + t * 1280 + ks * 32);
            uint32_t b[4][4];
#pragma unroll
            for (int j = 0; j < 4; ++j)
                ldsm_x4(b[j][0], b[j][1], b[j][2], b[j][3],
                        bs_base[stage] + b_lds + j * 1280 + ks * 32);
#pragma unroll
            for (int t = 0; t < 2; ++t)
#pragma unroll
                for (int j = 0; j < 4; ++j) {
                    mma_bf16(d[t][2 * j + 0], a[t], b[j][0], b[j][2]);
                    mma_bf16(d[t][2 * j + 1], a[t], b[j][1], b[j][3]);
                }
        }
        __syncthreads();
    }

    // epilogue: scale by 20, store fp32 logits
#pragma unroll
    for (int t = 0; t < 2; ++t) {
        const int mrow = m0 + wm * 32 + t * 16 + (lane >> 2);
#pragma unroll
        for (int j = 0; j < 8; ++j) {
            const int col = n0 + wn * 64 + j * 8 + (lane & 3) * 2;
            float2 lo2 = make_float2(d[t][j][0] * TEMP_INV, d[t][j][1] * TEMP_INV);
            float2 hi2 = make_float2(d[t][j][2] * TEMP_INV, d[t][j][3] * TEMP_INV);
            *(float2*)(g_logits + (size_t)mrow * P_DIM + col) = lo2;
            *(float2*)(g_logits + (size_t)(mrow + 8) * P_DIM + col) = hi2;
        }
    }
}

// ---------------------------------------------------------------------------
// Kernel 3: per-row logsumexp + NLL contribution (one block per batch row)
// ---------------------------------------------------------------------------
__global__ __launch_bounds__(256) void lse_loss_kernel(float* __restrict__ loss)
{
    const int b = blockIdx.x;
    const int tid = threadIdx.x;
    const float* row = g_logits + (size_t)b * P_DIM;
    __shared__ float sh[256];

    float mx = -CUDART_INF_F;
    for (int i = tid; i < P_DIM; i += 256) mx = fmaxf(mx, row[i]);
    sh[tid] = mx; __syncthreads();
    for (int s = 128; s > 0; s >>= 1) {
        if (tid < s) sh[tid] = fmaxf(sh[tid], sh[tid + s]);
        __syncthreads();
    }
    const float m = sh[0];
    __syncthreads();

    float acc = 0.0f;
    for (int i = tid; i < P_DIM; i += 256) acc += __expf(row[i] - m);
    sh[tid] = acc; __syncthreads();
    for (int s = 128; s > 0; s >>= 1) {
        if (tid < s) sh[tid] += sh[tid + s];
        __syncthreads();
    }

    if (tid == 0) {
        float lse = m + logf(sh[0]);
        float tgt = row[g_labels[b]];
        atomicAdd(loss, (lse - tgt) * (1.0f / (float)B_DIM));
    }
}

// ---------------------------------------------------------------------------
// Kernel 4: copy storage -> output (out storage base is d_out+1: 4B aligned)
// ---------------------------------------------------------------------------
__global__ __launch_bounds__(256) void copy_storage_kernel(
    const float* __restrict__ S, float* __restrict__ outS)
{
    size_t base = (size_t)blockIdx.x * 1024 + threadIdx.x;
#pragma unroll
    for (int k = 0; k < 4; ++k) {
        size_t idx = base + (size_t)k * 256;
        outS[idx] = S[idx];
    }
}

// ---------------------------------------------------------------------------
// Kernel 5: sequential momentum-EMA scatter + renorm (first-occurrence blocks
// replay the full duplicate chain, matching the reference scan semantics)
// ---------------------------------------------------------------------------
__global__ __launch_bounds__(256) void ema_update_kernel(
    const float* __restrict__ X,
    const float* __restrict__ S,
    float* __restrict__ outS)
{
    const int b = blockIdx.x;
    const int lab = g_labels[b];

    for (int b2 = 0; b2 < b; ++b2)
        if (g_labels[b2] == lab) return;

    const int tid = threadIdx.x;
    __shared__ float sh[256];

    float r[8];
    const float* srow = S + (size_t)lab * D_DIM;
#pragma unroll
    for (int i = 0; i < 8; ++i) r[i] = srow[tid + i * 256];

    for (int b2 = b; b2 < B_DIM; ++b2) {
        if (g_labels[b2] != lab) continue;
        const float* x = X + (size_t)b2 * D_DIM;
        float ss = 0.0f;
#pragma unroll
        for (int i = 0; i < 8; ++i) {
            r[i] = MOMENTUM * r[i] + (1.0f - MOMENTUM) * x[tid + i * 256];
            ss = fmaf(r[i], r[i], ss);
        }
        sh[tid] = ss; __syncthreads();
        for (int s = 128; s > 0; s >>= 1) {
            if (tid < s) sh[tid] += sh[tid + s];
            __syncthreads();
        }
        float inv = 1.0f / sqrtf(sh[0]);
        __syncthreads();
#pragma unroll
        for (int i = 0; i < 8; ++i) r[i] *= inv;
    }

    float* orow = outS + (size_t)lab * D_DIM;
#pragma unroll
    for (int i = 0; i < 8; ++i) orow[tid + i * 256] = r[i];
}

// ---------------------------------------------------------------------------
extern "C" void kernel_launch(void* const* d_in, const int* in_sizes, int n_in,
                              void* d_out, int out_size)
{
    const float* X      = (const float*)d_in[0];
    const float* S      = (const float*)d_in[1];
    const void*  alabel = d_in[4];

    float* out  = (float*)d_out;
    float* loss = out;
    float* outS = out + 1;

    static __nv_bfloat16 *Ah_p = nullptr, *Al_p = nullptr, *Sh_p = nullptr, *Sl_p = nullptr;
    if (!Ah_p) {
        cudaGetSymbolAddress((void**)&Ah_p, g_Ah);
        cudaGetSymbolAddress((void**)&Al_p, g_Al);
        cudaGetSymbolAddress((void**)&Sh_p, g_Sh);
        cudaGetSymbolAddress((void**)&Sl_p, g_Sl);
    }

    prologue_kernel<<<1, 256>>>(alabel, loss);

    split_kernel<<<(B_DIM * D_DIM) / 1024, 256>>>(X, Ah_p, Al_p);
    split_kernel<<<(P_DIM * D_DIM) / 1024, 256>>>(S, Sh_p, Sl_p);

    dim3 ggrid(B_DIM / 128, P_DIM / 128);   // 8 x 128 (m-major waves)
    gemm_mma_kernel<<<ggrid, 256>>>();

    lse_loss_kernel<<<B_DIM, 256>>>(loss);

    copy_storage_kernel<<<(P_DIM * D_DIM) / 1024, 256>>>(S, outS);

    ema_update_kernel<<<B_DIM, 256>>>(X, S, outS);
}